// round 2
// baseline (speedup 1.0000x reference)
#include <cuda_runtime.h>
#include <cstdint>

// GCN 2-layer: N=10000 nodes, d=128 feats, E=640000 edges (+ self loops).
// edges dtype is INT32 (JAX x64 disabled => jnp.int64 silently int32).
//
// Pipeline per call (graph-capturable, allocation-free):
//   1. deg[dst]++ (self-loop => init 1.0), dinv = rsqrt(deg)
//   2. h = x @ W1            (tiled fp32 GEMM)
//   3. out1 = b1 + h*dinv^2  (self-loop term + bias)
//   4. out1[dst] += h[src]*dinv[src]*dinv[dst]  (red.global.add.v4.f32)
//   5..7. same with W2/b2 into d_out

#define DF 128
#define MAXN 10048

__device__ float  g_deg [MAXN];
__device__ float  g_dinv[MAXN];
__device__ float4 g_h   [MAXN * (DF / 4)];   // post-GEMM features (both layers)
__device__ float4 g_x1  [MAXN * (DF / 4)];   // layer-1 output = layer-2 input

// ---------------------------------------------------------------------------
__global__ void k_init_deg(int n) {
    int i = blockIdx.x * blockDim.x + threadIdx.x;
    if (i < n) g_deg[i] = 1.0f;   // self loop
}

__global__ void k_count_deg(const int* __restrict__ edges, int E) {
    int e = blockIdx.x * blockDim.x + threadIdx.x;
    if (e < E) {
        int dst = edges[E + e];
        atomicAdd(&g_deg[dst], 1.0f);
    }
}

__global__ void k_dinv(int n) {
    int i = blockIdx.x * blockDim.x + threadIdx.x;
    if (i < n) g_dinv[i] = rsqrtf(g_deg[i]);
}

// ---------------------------------------------------------------------------
// Y[n,128] = X[n,128] @ W[128,128]
// Block: 64 rows, 256 threads. Thread: 8 rows x 4 cols (float4 accum per row).
__global__ void k_gemm(const float4* __restrict__ X4, const float* __restrict__ W,
                       float4* __restrict__ Y4, int n) {
    __shared__ float4 xs4[64 * 32];
    const float4* W4 = (const float4*)W;

    int tid  = threadIdx.x;
    int row0 = blockIdx.x * 64;

    // Load 64x128 tile of X into smem (64*32 float4 = 2048, 8 per thread)
#pragma unroll
    for (int j = 0; j < 8; j++) {
        int idx = tid + 256 * j;           // float4 index in tile
        int r   = idx >> 5;                // local row
        int gr  = row0 + r;
        xs4[idx] = (gr < n) ? X4[gr * 32 + (idx & 31)]
                            : make_float4(0.f, 0.f, 0.f, 0.f);
    }
    __syncthreads();

    int c4 = tid & 31;    // float4 column group (cols c4*4 .. c4*4+3)
    int rg = tid >> 5;    // 0..7 ; rows rg, rg+8, ..., rg+56

    float4 acc[8];
#pragma unroll
    for (int i = 0; i < 8; i++) acc[i] = make_float4(0.f, 0.f, 0.f, 0.f);

#pragma unroll 4
    for (int k0 = 0; k0 < 128; k0 += 4) {
        float4 w0 = __ldg(&W4[(k0 + 0) * 32 + c4]);
        float4 w1 = __ldg(&W4[(k0 + 1) * 32 + c4]);
        float4 w2 = __ldg(&W4[(k0 + 2) * 32 + c4]);
        float4 w3 = __ldg(&W4[(k0 + 3) * 32 + c4]);
#pragma unroll
        for (int i = 0; i < 8; i++) {
            int r = rg + 8 * i;
            float4 a = xs4[r * 32 + (k0 >> 2)];   // x[r][k0..k0+3], warp-broadcast
            acc[i].x += a.x * w0.x + a.y * w1.x + a.z * w2.x + a.w * w3.x;
            acc[i].y += a.x * w0.y + a.y * w1.y + a.z * w2.y + a.w * w3.y;
            acc[i].z += a.x * w0.z + a.y * w1.z + a.z * w2.z + a.w * w3.z;
            acc[i].w += a.x * w0.w + a.y * w1.w + a.z * w2.w + a.w * w3.w;
        }
    }

#pragma unroll
    for (int i = 0; i < 8; i++) {
        int gr = row0 + rg + 8 * i;
        if (gr < n) Y4[gr * 32 + c4] = acc[i];
    }
}

// ---------------------------------------------------------------------------
// out[n,:] = b + h[n,:] * dinv[n]^2   (bias + self-loop contribution)
__global__ void k_init_out(const float4* __restrict__ h, const float* __restrict__ b,
                           float4* __restrict__ out, int n) {
    int t = blockIdx.x * blockDim.x + threadIdx.x;
    if (t < n * 32) {
        int node = t >> 5;
        int c4   = t & 31;
        float dv = g_dinv[node];
        float s  = dv * dv;
        float4 hv = h[t];
        float4 bv = ((const float4*)b)[c4];
        float4 o;
        o.x = bv.x + hv.x * s;
        o.y = bv.y + hv.y * s;
        o.z = bv.z + hv.z * s;
        o.w = bv.w + hv.w * s;
        out[t] = o;
    }
}

// ---------------------------------------------------------------------------
// out[dst,:] += h[src,:] * dinv[src]*dinv[dst]
// One warp per edge: lane = float4 chunk. All feature data is L2-resident.
__global__ void k_scatter(const float4* __restrict__ h,
                          const int* __restrict__ edges,
                          float4* __restrict__ out, int E) {
    int t = blockIdx.x * blockDim.x + threadIdx.x;
    if (t < E * 32) {
        int e   = t >> 5;
        int c4  = t & 31;
        int src = edges[e];
        int dst = edges[E + e];
        float nrm = g_dinv[src] * g_dinv[dst];
        float4 hv = h[src * 32 + c4];
        float vx = hv.x * nrm, vy = hv.y * nrm, vz = hv.z * nrm, vw = hv.w * nrm;
        float4* p = out + dst * 32 + c4;
        asm volatile("red.global.add.v4.f32 [%0], {%1,%2,%3,%4};"
                     :: "l"(p), "f"(vx), "f"(vy), "f"(vz), "f"(vw)
                     : "memory");
    }
}

// ---------------------------------------------------------------------------
extern "C" void kernel_launch(void* const* d_in, const int* in_sizes, int n_in,
                              void* d_out, int out_size) {
    const float* x     = (const float*)d_in[0];
    const int*   edges = (const int*)d_in[1];      // int32 (JAX x64 off)
    const float* W1    = (const float*)d_in[2];
    const float* b1    = (const float*)d_in[3];
    const float* W2    = (const float*)d_in[4];
    const float* b2    = (const float*)d_in[5];
    float4*      out   = (float4*)d_out;

    int N = in_sizes[0] / DF;     // 10000
    int E = in_sizes[1] / 2;      // 640000

    const int T = 256;
    int gN    = (N + T - 1) / T;
    int gE    = (E + T - 1) / T;
    int gNF   = (N * 32 + T - 1) / T;
    int gEF   = (E * 32 + T - 1) / T;
    int gGemm = (N + 63) / 64;

    // norm
    k_init_deg<<<gN, T>>>(N);
    k_count_deg<<<gE, T>>>(edges, E);
    k_dinv<<<gN, T>>>(N);

    // layer 1
    k_gemm<<<gGemm, T>>>((const float4*)x, W1, g_h, N);
    k_init_out<<<gNF, T>>>(g_h, b1, g_x1, N);
    k_scatter<<<gEF, T>>>(g_h, edges, g_x1, E);

    // layer 2
    k_gemm<<<gGemm, T>>>((const float4*)g_x1, W2, g_h, N);
    k_init_out<<<gNF, T>>>(g_h, b2, out, N);
    k_scatter<<<gEF, T>>>(g_h, edges, out, E);
}

// round 3
// speedup vs baseline: 1.4420x; 1.4420x over previous
#include <cuda_runtime.h>
#include <cstdint>

// GCN 2-layer: N=10000, d=128, E=640000 (+self loops), edges int32.
// Strategy: build CSR (by dst) in-graph each call, then PULL aggregation
// (warp per node, register accumulation) -> zero float atomics.

#define DF 128
#define MAXN 10048
#define MAXE 650000

__device__ int    g_degi  [MAXN];       // in-degree (real edges only)
__device__ int    g_rowptr[MAXN + 1];
__device__ int    g_cursor[MAXN];
__device__ float  g_dinv  [MAXN];
__device__ int    g_esrc  [MAXE];       // CSR: src per slot
__device__ float  g_enorm [MAXE];       // CSR: dinv[src]*dinv[dst] per slot
__device__ float4 g_h     [MAXN * (DF / 4)];   // post-GEMM features
__device__ float4 g_x1    [MAXN * (DF / 4)];   // layer-1 output

// ---------------------------------------------------------------------------
__global__ void k_zero(int n) {
    int i = blockIdx.x * blockDim.x + threadIdx.x;
    if (i < n) g_degi[i] = 0;
}

__global__ void k_count(const int* __restrict__ edges, int E) {
    int e = blockIdx.x * blockDim.x + threadIdx.x;
    if (e < E) atomicAdd(&g_degi[edges[E + e]], 1);
}

__global__ void k_dinv(int n) {
    int i = blockIdx.x * blockDim.x + threadIdx.x;
    if (i < n) g_dinv[i] = rsqrtf((float)(g_degi[i] + 1));   // +1 self loop
}

// Single-block exclusive scan of g_degi[0..n) -> g_rowptr, g_cursor.
__global__ void k_scan(int n) {
    __shared__ int s[1024];
    int tid = threadIdx.x;
    int per = (n + 1023) >> 10;          // elems per thread (<=16 for n<=16384)
    int base = tid * per;

    int local[16];
    int sum = 0;
#pragma unroll
    for (int j = 0; j < 16; j++) {
        if (j < per) {
            int idx = base + j;
            int v = (idx < n) ? g_degi[idx] : 0;
            local[j] = sum;
            sum += v;
        }
    }
    s[tid] = sum;
    __syncthreads();

    // Hillis-Steele inclusive scan over 1024 partials
    for (int off = 1; off < 1024; off <<= 1) {
        int v = (tid >= off) ? s[tid - off] : 0;
        __syncthreads();
        s[tid] += v;
        __syncthreads();
    }

    int pre = (tid == 0) ? 0 : s[tid - 1];
#pragma unroll
    for (int j = 0; j < 16; j++) {
        if (j < per) {
            int idx = base + j;
            if (idx < n) {
                int p = pre + local[j];
                g_rowptr[idx] = p;
                g_cursor[idx] = p;
            }
        }
    }
    if (tid == 1023) g_rowptr[n] = s[1023];
}

__global__ void k_fill(const int* __restrict__ edges, int E) {
    int e = blockIdx.x * blockDim.x + threadIdx.x;
    if (e < E) {
        int src = edges[e];
        int dst = edges[E + e];
        int pos = atomicAdd(&g_cursor[dst], 1);
        g_esrc[pos]  = src;
        g_enorm[pos] = g_dinv[src] * g_dinv[dst];
    }
}

// ---------------------------------------------------------------------------
// Y[n,128] = X[n,128] @ W[128,128]
// Block: 32 rows, 256 threads. Thread: 4 rows x 4 cols (float4 accum per row).
__global__ void k_gemm(const float4* __restrict__ X4, const float* __restrict__ W,
                       float4* __restrict__ Y4, int n) {
    __shared__ float4 xs4[32 * 32];
    const float4* W4 = (const float4*)W;

    int tid  = threadIdx.x;
    int row0 = blockIdx.x * 32;

    // Load 32x128 tile of X into smem (1024 float4, 4 per thread)
#pragma unroll
    for (int j = 0; j < 4; j++) {
        int idx = tid + 256 * j;
        int gr  = row0 + (idx >> 5);
        xs4[idx] = (gr < n) ? X4[gr * 32 + (idx & 31)]
                            : make_float4(0.f, 0.f, 0.f, 0.f);
    }
    __syncthreads();

    int c4 = tid & 31;    // float4 column group
    int rg = tid >> 5;    // 0..7 ; rows rg, rg+8, rg+16, rg+24

    float4 acc[4];
#pragma unroll
    for (int i = 0; i < 4; i++) acc[i] = make_float4(0.f, 0.f, 0.f, 0.f);

#pragma unroll 4
    for (int k0 = 0; k0 < 128; k0 += 4) {
        float4 w0 = __ldg(&W4[(k0 + 0) * 32 + c4]);
        float4 w1 = __ldg(&W4[(k0 + 1) * 32 + c4]);
        float4 w2 = __ldg(&W4[(k0 + 2) * 32 + c4]);
        float4 w3 = __ldg(&W4[(k0 + 3) * 32 + c4]);
#pragma unroll
        for (int i = 0; i < 4; i++) {
            float4 a = xs4[(rg + 8 * i) * 32 + (k0 >> 2)];
            acc[i].x += a.x * w0.x + a.y * w1.x + a.z * w2.x + a.w * w3.x;
            acc[i].y += a.x * w0.y + a.y * w1.y + a.z * w2.y + a.w * w3.y;
            acc[i].z += a.x * w0.z + a.y * w1.z + a.z * w2.z + a.w * w3.z;
            acc[i].w += a.x * w0.w + a.y * w1.w + a.z * w2.w + a.w * w3.w;
        }
    }

#pragma unroll
    for (int i = 0; i < 4; i++) {
        int gr = row0 + rg + 8 * i;
        if (gr < n) Y4[gr * 32 + c4] = acc[i];
    }
}

// ---------------------------------------------------------------------------
// Pull aggregation: out[v,:] = b + h[v,:]*dinv[v]^2 + sum_{e in CSR[v]} h[src]*norm
// One warp per node; lane = float4 chunk of the 128-float row.
__global__ void k_agg(const float4* __restrict__ h, const float* __restrict__ b,
                      float4* __restrict__ out, int n) {
    int node = blockIdx.x * (blockDim.x >> 5) + (threadIdx.x >> 5);
    int lane = threadIdx.x & 31;
    if (node >= n) return;

    int beg = g_rowptr[node];
    int end = g_rowptr[node + 1];
    float dv = g_dinv[node];
    float s  = dv * dv;

    float4 bv = ((const float4*)b)[lane];
    float4 hv = h[node * 32 + lane];
    float ax = bv.x + hv.x * s;
    float ay = bv.y + hv.y * s;
    float az = bv.z + hv.z * s;
    float aw = bv.w + hv.w * s;

    int j = beg;
    for (; j + 4 <= end; j += 4) {
        int   s0 = g_esrc[j],     s1 = g_esrc[j + 1];
        int   s2 = g_esrc[j + 2], s3 = g_esrc[j + 3];
        float n0 = g_enorm[j],     n1 = g_enorm[j + 1];
        float n2 = g_enorm[j + 2], n3 = g_enorm[j + 3];
        float4 v0 = h[s0 * 32 + lane];
        float4 v1 = h[s1 * 32 + lane];
        float4 v2 = h[s2 * 32 + lane];
        float4 v3 = h[s3 * 32 + lane];
        ax += v0.x * n0 + v1.x * n1 + v2.x * n2 + v3.x * n3;
        ay += v0.y * n0 + v1.y * n1 + v2.y * n2 + v3.y * n3;
        az += v0.z * n0 + v1.z * n1 + v2.z * n2 + v3.z * n3;
        aw += v0.w * n0 + v1.w * n1 + v2.w * n2 + v3.w * n3;
    }
    for (; j < end; j++) {
        int   sj = g_esrc[j];
        float nj = g_enorm[j];
        float4 v = h[sj * 32 + lane];
        ax += v.x * nj;
        ay += v.y * nj;
        az += v.z * nj;
        aw += v.w * nj;
    }

    out[node * 32 + lane] = make_float4(ax, ay, az, aw);
}

// ---------------------------------------------------------------------------
extern "C" void kernel_launch(void* const* d_in, const int* in_sizes, int n_in,
                              void* d_out, int out_size) {
    const float* x     = (const float*)d_in[0];
    const int*   edges = (const int*)d_in[1];      // int32 (JAX x64 off)
    const float* W1    = (const float*)d_in[2];
    const float* b1    = (const float*)d_in[3];
    const float* W2    = (const float*)d_in[4];
    const float* b2    = (const float*)d_in[5];
    float4*      out   = (float4*)d_out;

    int N = in_sizes[0] / DF;     // 10000
    int E = in_sizes[1] / 2;      // 640000

    const int T = 256;
    int gN    = (N + T - 1) / T;
    int gE    = (E + T - 1) / T;
    int gGemm = (N + 31) / 32;
    int gAgg  = (N + 7) / 8;      // 8 warps per block

    // CSR build + norm
    k_zero <<<gN, T>>>(N);
    k_count<<<gE, T>>>(edges, E);
    k_dinv <<<gN, T>>>(N);
    k_scan <<<1, 1024>>>(N);
    k_fill <<<gE, T>>>(edges, E);

    // layer 1
    k_gemm<<<gGemm, T>>>((const float4*)x, W1, g_h, N);
    k_agg <<<gAgg, T>>>(g_h, b1, g_x1, N);

    // layer 2
    k_gemm<<<gGemm, T>>>(g_x1, W2, g_h, N);
    k_agg <<<gAgg, T>>>(g_h, b2, out, N);
}

// round 5
// speedup vs baseline: 1.4552x; 1.0092x over previous
#include <cuda_runtime.h>
#include <cstdint>

// GCN 2-layer: N=10000, d=128, E=640000 (+self loops), edges int32.
// CSR-by-dst pull aggregation, zero float atomics.
// Launch order (agg1 is 4th => profiled by the fixed ncu window):
//   1 k_count          deg[dst]++ (global int atomics; g_degi starts zeroed)
//   2 k_scandinv       exclusive scan -> rowptr/cursor, dinv, re-zero degi
//   3 k_gemmfill       blocks [0,nGemm): h = x@W1 ; blocks [nGemm,..): CSR fill
//   4 k_agg            out1 = b1 + selfloop + pull-sum   <-- profiled
//   5 k_gemm           h = out1@W2
//   6 k_agg            out  = b2 + selfloop + pull-sum

#define DF 128
#define MAXN 10048
#define MAXE 650000

__device__ int    g_degi  [MAXN];       // zero-initialized at module load
__device__ int    g_rowptr[MAXN + 1];
__device__ int    g_cursor[MAXN];
__device__ float  g_dinv  [MAXN];
__device__ float2 g_epack [MAXE];       // .x = src (int bits), .y = norm
__device__ float4 g_h     [MAXN * (DF / 4)];
__device__ float4 g_x1    [MAXN * (DF / 4)];

// ---------------------------------------------------------------------------
__global__ void k_count(const int* __restrict__ edges, int E) {
    int e = blockIdx.x * blockDim.x + threadIdx.x;
    if (e < E) atomicAdd(&g_degi[edges[E + e]], 1);
}

// Single-block: exclusive scan of degi -> rowptr/cursor, dinv = rsqrt(deg+1),
// and re-zero degi so the next graph replay starts clean.
__global__ void k_scandinv(int n) {
    __shared__ int s[1024];
    int tid  = threadIdx.x;
    int per  = (n + 1023) >> 10;
    int base = tid * per;

    int local[16];
    int sum = 0;
#pragma unroll
    for (int j = 0; j < 16; j++) {
        if (j < per) {
            int idx = base + j;
            int v = (idx < n) ? g_degi[idx] : 0;
            local[j] = sum;
            sum += v;
            if (idx < n) {
                g_dinv[idx] = rsqrtf((float)(v + 1));  // +1 self loop
                g_degi[idx] = 0;                       // reset for next call
            }
        }
    }
    s[tid] = sum;
    __syncthreads();

    for (int off = 1; off < 1024; off <<= 1) {
        int v = (tid >= off) ? s[tid - off] : 0;
        __syncthreads();
        s[tid] += v;
        __syncthreads();
    }

    int pre = (tid == 0) ? 0 : s[tid - 1];
#pragma unroll
    for (int j = 0; j < 16; j++) {
        if (j < per) {
            int idx = base + j;
            if (idx < n) {
                int p = pre + local[j];
                g_rowptr[idx] = p;
                g_cursor[idx] = p;
            }
        }
    }
    if (tid == 1023) g_rowptr[n] = s[1023];
}

// ---------------------------------------------------------------------------
// GEMM body: Y[n,128] = X[n,128] @ W[128,128]; 32 rows/block, 256 threads.
__device__ __forceinline__ void gemm_body(const float4* __restrict__ X4,
                                          const float* __restrict__ W,
                                          float4* __restrict__ Y4,
                                          int n, int bid) {
    __shared__ float4 xs4[32 * 32];
    const float4* W4 = (const float4*)W;

    int tid  = threadIdx.x;
    int row0 = bid * 32;

#pragma unroll
    for (int j = 0; j < 4; j++) {
        int idx = tid + 256 * j;
        int gr  = row0 + (idx >> 5);
        xs4[idx] = (gr < n) ? X4[gr * 32 + (idx & 31)]
                            : make_float4(0.f, 0.f, 0.f, 0.f);
    }
    __syncthreads();

    int c4 = tid & 31;
    int rg = tid >> 5;

    float4 acc[4];
#pragma unroll
    for (int i = 0; i < 4; i++) acc[i] = make_float4(0.f, 0.f, 0.f, 0.f);

#pragma unroll 4
    for (int k0 = 0; k0 < 128; k0 += 4) {
        float4 w0 = __ldg(&W4[(k0 + 0) * 32 + c4]);
        float4 w1 = __ldg(&W4[(k0 + 1) * 32 + c4]);
        float4 w2 = __ldg(&W4[(k0 + 2) * 32 + c4]);
        float4 w3 = __ldg(&W4[(k0 + 3) * 32 + c4]);
#pragma unroll
        for (int i = 0; i < 4; i++) {
            float4 a = xs4[(rg + 8 * i) * 32 + (k0 >> 2)];
            acc[i].x += a.x * w0.x + a.y * w1.x + a.z * w2.x + a.w * w3.x;
            acc[i].y += a.x * w0.y + a.y * w1.y + a.z * w2.y + a.w * w3.y;
            acc[i].z += a.x * w0.z + a.y * w1.z + a.z * w2.z + a.w * w3.z;
            acc[i].w += a.x * w0.w + a.y * w1.w + a.z * w2.w + a.w * w3.w;
        }
    }

#pragma unroll
    for (int i = 0; i < 4; i++) {
        int gr = row0 + rg + 8 * i;
        if (gr < n) Y4[gr * 32 + c4] = acc[i];
    }
}

__global__ void k_gemm(const float4* __restrict__ X4, const float* __restrict__ W,
                       float4* __restrict__ Y4, int n) {
    gemm_body(X4, W, Y4, n, blockIdx.x);
}

// Fused: first nGemm blocks do layer-1 GEMM; the rest bucket edges into CSR.
__global__ void k_gemmfill(const float4* __restrict__ X4, const float* __restrict__ W,
                           float4* __restrict__ Y4, int n,
                           const int* __restrict__ edges, int E, int nGemm) {
    if (blockIdx.x >= nGemm) {
        int stride = (gridDim.x - nGemm) * blockDim.x;
        for (int e = (blockIdx.x - nGemm) * blockDim.x + threadIdx.x;
             e < E; e += stride) {
            int src = edges[e];
            int dst = edges[E + e];
            int pos = atomicAdd(&g_cursor[dst], 1);
            g_epack[pos] = make_float2(__int_as_float(src),
                                       g_dinv[src] * g_dinv[dst]);
        }
        return;
    }
    gemm_body(X4, W, Y4, n, blockIdx.x);
}

// ---------------------------------------------------------------------------
// Pull aggregation: out[v,:] = b + h[v,:]*dinv[v]^2 + sum_e h[src_e,:]*norm_e
// One warp per node; lane = float4 chunk. Indices are loaded cooperatively
// (32 edges per LDG.64 round) and distributed by shfl -> per-edge cost is
// 2 SHFL + 1 LDG.128 + 4 FMA with up to 32 gathers in flight.
__global__ void __launch_bounds__(256) k_agg(
        const float4* __restrict__ h, const float* __restrict__ b,
        float4* __restrict__ out, int n) {
    int node = blockIdx.x * (blockDim.x >> 5) + (threadIdx.x >> 5);
    int lane = threadIdx.x & 31;
    if (node >= n) return;

    int beg = g_rowptr[node];
    int end = g_rowptr[node + 1];
    float dv = g_dinv[node];
    float s  = dv * dv;

    float4 bv = __ldg(&((const float4*)b)[lane]);
    float4 hv = h[node * 32 + lane];
    float ax = fmaf(hv.x, s, bv.x);
    float ay = fmaf(hv.y, s, bv.y);
    float az = fmaf(hv.z, s, bv.z);
    float aw = fmaf(hv.w, s, bv.w);

    for (int base = beg; base < end; base += 32) {
        int m = end - base;                 // edges left (>0)
        int   my_src = 0;
        float my_nrm = 0.f;
        if (lane < m) {
            float2 p = g_epack[base + lane];
            my_src = __float_as_int(p.x);
            my_nrm = p.y;
        }
        if (m >= 32) {
#pragma unroll
            for (int t = 0; t < 32; t++) {
                int   src = __shfl_sync(0xffffffffu, my_src, t);
                float nm  = __shfl_sync(0xffffffffu, my_nrm, t);
                float4 v = h[src * 32 + lane];
                ax = fmaf(v.x, nm, ax);
                ay = fmaf(v.y, nm, ay);
                az = fmaf(v.z, nm, az);
                aw = fmaf(v.w, nm, aw);
            }
        } else {
            for (int t = 0; t < m; t++) {
                int   src = __shfl_sync(0xffffffffu, my_src, t);
                float nm  = __shfl_sync(0xffffffffu, my_nrm, t);
                float4 v = h[src * 32 + lane];
                ax = fmaf(v.x, nm, ax);
                ay = fmaf(v.y, nm, ay);
                az = fmaf(v.z, nm, az);
                aw = fmaf(v.w, nm, aw);
            }
        }
    }

    out[node * 32 + lane] = make_float4(ax, ay, az, aw);
}

// ---------------------------------------------------------------------------
extern "C" void kernel_launch(void* const* d_in, const int* in_sizes, int n_in,
                              void* d_out, int out_size) {
    const float* x     = (const float*)d_in[0];
    const int*   edges = (const int*)d_in[1];      // int32 (JAX x64 off)
    const float* W1    = (const float*)d_in[2];
    const float* b1    = (const float*)d_in[3];
    const float* W2    = (const float*)d_in[4];
    const float* b2    = (const float*)d_in[5];
    float4*      out   = (float4*)d_out;

    int N = in_sizes[0] / DF;     // 10000
    int E = in_sizes[1] / 2;      // 640000

    const int T = 256;
    int gE    = (E + T - 1) / T;
    int nGemm = (N + 31) / 32;
    int gFill = 1024;                       // grid-stride fill blocks
    int gAgg  = (N + 7) / 8;                // 8 warps per block

    // 1: degree count (g_degi is zero at first call; k_scandinv re-zeroes it)
    k_count<<<gE, T>>>(edges, E);
    // 2: scan + dinv + reset
    k_scandinv<<<1, 1024>>>(N);
    // 3: fused layer-1 GEMM + CSR fill
    k_gemmfill<<<nGemm + gFill, T>>>((const float4*)x, W1, g_h, N, edges, E, nGemm);
    // 4: layer-1 aggregation  (profiled launch)
    k_agg<<<gAgg, T>>>(g_h, b1, g_x1, N);
    // 5: layer-2 GEMM
    k_gemm<<<nGemm, T>>>(g_x1, W2, g_h, N);
    // 6: layer-2 aggregation
    k_agg<<<gAgg, T>>>(g_h, b2, out, N);
}